// round 14
// baseline (speedup 1.0000x reference)
#include <cuda_runtime.h>
#include <cuda_fp16.h>
#include <cstdint>

// ---------------------------------------------------------------------------
// CliffordEPModel collapsed:
//   pred[b,o] = sum_{ma} x[b,ma] * A[ma,o]                           (main MMA)
//   A[ma,o]   = c * sum_{hk} coef(a,k) * Win[h, m*8+(a^k)] * Wout[o, hk]
//   c = 1 - 0.9^20 ;  coef(a,k) = sgn(k,k)*sgn(a,a^k)  (Cl(3,0) Cayley)
// Both GEMMs mma.sync m16n8k16 fp16 (fp32 accum).
// This round: warps-in-flight. prep 256->512 CTAs (NSLICE 32); main 512->1024
// warps via K-split-2 with smem combine, keeping X single-read + pipelined.
// ---------------------------------------------------------------------------

#define BATCH   8192
#define NSLICE  32                      // split-K for prep (hk slices of 128)
#define C_RELAX 0.8784233454094307f     // 1 - 0.9^20

// scratch
__device__ __align__(16) float g_P[NSLICE][512 * 64];   // prep partials [ma][o], 4 MB
__device__ __align__(16) uint4 g_Bpk[4096];             // packed fp16 B-frags, 64 KB

__device__ __forceinline__ float blade_sign(int a, int b) {
    int e = (b & 1) * (((a >> 1) & 1) + ((a >> 2) & 1)) + ((b >> 1) & 1) * ((a >> 2) & 1);
    return (e & 1) ? -1.0f : 1.0f;
}

__device__ __forceinline__ uint32_t smem_u32(const void* p) {
    uint32_t a;
    asm("{ .reg .u64 t; cvta.to.shared.u64 t, %1; cvt.u32.u64 %0, t; }" : "=r"(a) : "l"(p));
    return a;
}

__device__ __forceinline__ void ldsm_x4(uint32_t* r, uint32_t addr) {
    asm volatile("ldmatrix.sync.aligned.m8n8.x4.shared.b16 {%0,%1,%2,%3}, [%4];"
                 : "=r"(r[0]), "=r"(r[1]), "=r"(r[2]), "=r"(r[3]) : "r"(addr));
}

__device__ __forceinline__ void mma_fp16(float* c, const uint32_t* a, uint32_t b0, uint32_t b1) {
    asm volatile(
        "mma.sync.aligned.m16n8k16.row.col.f32.f16.f16.f32 "
        "{%0,%1,%2,%3}, {%4,%5,%6,%7}, {%8,%9}, {%0,%1,%2,%3};"
        : "+f"(c[0]), "+f"(c[1]), "+f"(c[2]), "+f"(c[3])
        : "r"(a[0]), "r"(a[1]), "r"(a[2]), "r"(a[3]), "r"(b0), "r"(b1));
}

__device__ __forceinline__ uint32_t h2pack(float lo, float hi) {
    __half2 h = __floats2half2_rn(lo, hi);
    return *reinterpret_cast<uint32_t*>(&h);
}

// ---------------------------------------------------------------------------
// Kernel 1: prep GEMM (smem-staged, split-K).
//   P[s][ma, o] = sum_{hk in slice s} coef(a,k)*Win[h, m8+(a^k)] * Wout[o, hk]
// grid (8 ma-tiles, 2 o-tiles, 32 slices) = 512 CTAs, 256 threads.
// Per CTA: 64 ma x 32 o, K = 128 (16 h). smem 26 KB -> grid-limited 3.5 CTA/SM.
// All global loads issued before converts (MLP). Row pitch 272 B.
// ---------------------------------------------------------------------------
#define P_ROW    272
#define P_AS     0
#define P_BS     (64 * P_ROW)
#define PREP_SMEM (96 * P_ROW)          // 26112

__global__ __launch_bounds__(256, 1) void prep_gemm_kernel(
        const float* __restrict__ Win, const float* __restrict__ Wout) {
    extern __shared__ char sm[];
    int tid = threadIdx.x;
    int w   = tid >> 5, l = tid & 31;
    int ma0 = blockIdx.x * 64;
    int ob0 = blockIdx.y * 32;
    int s   = blockIdx.z;               // hk slice (128 wide = 16 h)

    // ======== issue ALL global loads first ========
    float4 bv[4];
#pragma unroll
    for (int it = 0; it < 4; it++) {
        int idx = it * 256 + tid;       // 0..1023 float4 units
        int row = idx >> 5;             // o-local 0..31
        int c4  = idx & 31;             // float4 within 128-float row
        bv[it] = *(const float4*)&Wout[(ob0 + row) * 4096 + s * 128 + c4 * 4];
    }
    float4 w0 = make_float4(0.f, 0.f, 0.f, 0.f), w1 = w0;
    int m_local = tid & 7;
    int h_local = tid >> 3;             // 0..31 (only 0..15 used for A)
    if (h_local < 16) {
        int h  = s * 16 + h_local;
        int mg = blockIdx.x * 8 + m_local;
        w0 = *(const float4*)&Win[h * 512 + mg * 8];
        w1 = *(const float4*)&Win[h * 512 + mg * 8 + 4];
    }

    // ======== convert + store B tile ========
#pragma unroll
    for (int it = 0; it < 4; it++) {
        int idx = it * 256 + tid;
        int row = idx >> 5;
        int c4  = idx & 31;
        uint2 pk = make_uint2(h2pack(bv[it].x, bv[it].y), h2pack(bv[it].z, bv[it].w));
        *(uint2*)(sm + P_BS + row * P_ROW + c4 * 8) = pk;
    }
    // ======== convert + store A tile (Cayley gather + signs) ========
    if (h_local < 16) {
        float w8[8] = {w0.x, w0.y, w0.z, w0.w, w1.x, w1.y, w1.z, w1.w};
#pragma unroll
        for (int a = 0; a < 8; a++) {
            __half hv[8];
#pragma unroll
            for (int k = 0; k < 8; k++) {
                float coef = blade_sign(k, k) * blade_sign(a, a ^ k);
                hv[k] = __float2half_rn(coef * w8[a ^ k]);
            }
            *(uint4*)(sm + P_AS + (m_local * 8 + a) * P_ROW + h_local * 16) =
                *reinterpret_cast<uint4*>(hv);
        }
    }
    __syncthreads();

    // ---- compute: 8 warps = 4 m-groups x 2 n-groups; K=128 in 2 chunks ----
    int mg2 = w & 3, ng = w >> 2;
    int grp = l >> 3, rin = l & 7;
    uint32_t smb = smem_u32(sm);
    uint32_t aB  = smb + P_AS + (uint32_t)((mg2 * 16 + rin + (grp & 1) * 8) * P_ROW + (grp >> 1) * 16);
    uint32_t bB0 = smb + P_BS + (uint32_t)((ng * 16 + rin) * P_ROW + grp * 16);

    float acc[2][4];
#pragma unroll
    for (int t = 0; t < 2; t++)
#pragma unroll
        for (int q = 0; q < 4; q++) acc[t][q] = 0.f;

#pragma unroll
    for (int c = 0; c < 2; c++) {
        uint32_t Af[4][4];
#pragma unroll
        for (int ks = 0; ks < 4; ks++) ldsm_x4(Af[ks], aB + c * 128 + ks * 32);
#pragma unroll
        for (int t = 0; t < 2; t++) {
            uint32_t bf[8];
            uint32_t bB = bB0 + (uint32_t)(t * 8 * P_ROW + c * 128);
#pragma unroll
            for (int kp = 0; kp < 2; kp++) ldsm_x4(&bf[kp * 4], bB + kp * 64);
#pragma unroll
            for (int ks = 0; ks < 4; ks++)
                mma_fp16(acc[t], Af[ks], bf[ks * 2], bf[ks * 2 + 1]);
        }
    }

    // ---- epilogue: partial slab, [ma][o] layout, float2 stores ----
    float* dst = g_P[s];
    int ma_r = ma0 + mg2 * 16 + (l >> 2);
    int o_c  = ob0 + ng * 16 + (l & 3) * 2;
#pragma unroll
    for (int t = 0; t < 2; t++) {
        *(float2*)&dst[ma_r * 64 + o_c + t * 8]       = make_float2(acc[t][0], acc[t][1]);
        *(float2*)&dst[(ma_r + 8) * 64 + o_c + t * 8] = make_float2(acc[t][2], acc[t][3]);
    }
}

// ---------------------------------------------------------------------------
// Kernel 2: reduce split-K partials, *C_RELAX, fp16-cast, pack into main's
// B-fragment order. Loads lane-coalesced over o.
// ---------------------------------------------------------------------------
__global__ __launch_bounds__(256) void reduce_kernel() {
    int e = blockIdx.x * 256 + threadIdx.x;   // 0..16383
    int o = e & 63;
    int j = e >> 6;                           // k-pair index (k = 2j over ma)

    float s0 = 0.f, s1 = 0.f;
#pragma unroll
    for (int s = 0; s < NSLICE; s++) {
        s0 += g_P[s][(2 * j) * 64 + o];
        s1 += g_P[s][(2 * j + 1) * 64 + o];
    }
    uint32_t h = h2pack(s0 * C_RELAX, s1 * C_RELAX);

    int k   = 2 * j;
    int n   = o;
    int i   = k >> 6;                 // chunk
    int r   = k & 63;
    int ks  = r >> 4;
    int rem = r & 15;                 // even
    int cc  = rem >> 2;               // lane's c
    int comp = (ks & 1) * 2 + ((rem & 2) >> 1);
    int kp  = ks >> 1;
    int nt  = n >> 3;
    int lI  = ((n & 7) << 2) | cc;

    ((uint32_t*)g_Bpk)[((((i * 8 + nt) * 2 + kp) * 32) + lI) * 4 + comp] = h;
}

// ---------------------------------------------------------------------------
// Kernel 3: main GEMM, fragment-direct, K-split-2, software-pipelined.
//   out(8192,64) = X(8192,512) @ A(512,64)
// 256 blocks x 128 threads = 1024 warps (1.7/SMSP).
// Block = 2 row-groups x 2 k-halves; warp = 16 rows x 64 cols x K=256.
// Each X element loaded exactly once; next chunk's loads issued before the
// current chunk's 32 MMAs. k-half-1 dumps acc to smem; k-half-0 combines.
// ---------------------------------------------------------------------------
__global__ __launch_bounds__(128, 1) void main_kernel(
        const float* __restrict__ X, float* __restrict__ out) {
    __shared__ float red[2][8][32][4];   // 8 KB
    int w  = threadIdx.x >> 5;           // 0..3
    int l  = threadIdx.x & 31;
    int rg = w & 1;                      // row-group
    int kh = w >> 1;                     // k-half
    int r0 = blockIdx.x * 32 + rg * 16;
    int c  = l & 3, rY = l >> 2;

    float acc[8][4];
#pragma unroll
    for (int nt = 0; nt < 8; nt++)
#pragma unroll
        for (int q = 0; q < 4; q++) acc[nt][q] = 0.f;

    const float* x0 = X + (r0 + rY) * 512 + 4 * c;
    const float* x1 = x0 + 8 * 512;

    // prologue: first chunk of this k-half
    float4 lo[4], hi[4];
#pragma unroll
    for (int ks = 0; ks < 4; ks++) {
        lo[ks] = *(const float4*)(x0 + kh * 256 + ks * 16);
        hi[ks] = *(const float4*)(x1 + kh * 256 + ks * 16);
    }

#pragma unroll
    for (int ii = 0; ii < 4; ii++) {
        int i = kh * 4 + ii;
        uint32_t A[4][4];
#pragma unroll
        for (int ks = 0; ks < 4; ks++) {
            A[ks][0] = h2pack(lo[ks].x, lo[ks].y);
            A[ks][1] = h2pack(hi[ks].x, hi[ks].y);
            A[ks][2] = h2pack(lo[ks].z, lo[ks].w);
            A[ks][3] = h2pack(hi[ks].z, hi[ks].w);
        }
        if (ii < 3) {
            int k0 = (i + 1) * 64;
#pragma unroll
            for (int ks = 0; ks < 4; ks++) {
                lo[ks] = *(const float4*)(x0 + k0 + ks * 16);
                hi[ks] = *(const float4*)(x1 + k0 + ks * 16);
            }
        }
#pragma unroll
        for (int nt = 0; nt < 8; nt++) {
#pragma unroll
            for (int kp = 0; kp < 2; kp++) {
                uint4 b = g_Bpk[((i * 8 + nt) * 2 + kp) * 32 + l];
                mma_fp16(acc[nt], A[2 * kp],     b.x, b.y);
                mma_fp16(acc[nt], A[2 * kp + 1], b.z, b.w);
            }
        }
    }

    if (kh == 1) {
#pragma unroll
        for (int nt = 0; nt < 8; nt++)
            *(float4*)&red[rg][nt][l][0] = *(float4*)acc[nt];
    }
    __syncthreads();
    if (kh == 0) {
        int rr = r0 + rY;
        int cb = 2 * c;
#pragma unroll
        for (int nt = 0; nt < 8; nt++) {
            float4 v = *(float4*)&red[rg][nt][l][0];
            *(float2*)&out[rr * 64 + nt * 8 + cb] =
                make_float2(acc[nt][0] + v.x, acc[nt][1] + v.y);
            *(float2*)&out[(rr + 8) * 64 + nt * 8 + cb] =
                make_float2(acc[nt][2] + v.z, acc[nt][3] + v.w);
        }
    }
}

// ---------------------------------------------------------------------------
extern "C" void kernel_launch(void* const* d_in, const int* in_sizes, int n_in,
                              void* d_out, int out_size) {
    const float* x    = (const float*)d_in[0];   // (8192, 512)
    const float* Win  = (const float*)d_in[1];   // (512h, 512mb)
    const float* Wout = (const float*)d_in[2];   // (64, 4096)
    float* out        = (float*)d_out;           // (8192, 64)

    cudaFuncSetAttribute(prep_gemm_kernel,
                         cudaFuncAttributeMaxDynamicSharedMemorySize, PREP_SMEM);

    prep_gemm_kernel<<<dim3(8, 2, NSLICE), 256, PREP_SMEM>>>(Win, Wout);
    reduce_kernel<<<64, 256>>>();
    main_kernel<<<256, 128>>>(x, out);
}